// round 15
// baseline (speedup 1.0000x reference)
#include <cuda_runtime.h>
#include <cuda_bf16.h>
#include <cstdint>

#define B_SZ 4096
#define D_SZ 2048
#define E_SZ 16
#define C_SZ 1000
#define NPAD 1024

// int8 GEMM tiles
#define TM 128
#define TN 64
#define KC 64                    // s8 k per chunk
#define NCHUNK (D_SZ / KC)       // 32

// A smem: [m][k] rows of 64 s8 padded to 80B; B smem: [n][k] same
#define AROWB 80
#define A_TILE_B (128 * AROWB)   // 10240 per limb
#define B_TILE_B (64 * AROWB)    // 5120 per limb
#define OFF_A1 0
#define OFF_A2 A_TILE_B
#define OFF_B1 (2 * A_TILE_B)
#define OFF_B2 (2 * A_TILE_B + B_TILE_B)
#define STAGE_B (2 * A_TILE_B + 2 * B_TILE_B)   // 30720
#define NST 3
#define DYN_BYTES (NST * STAGE_B)               // 92160 -> still 2 CTAs/SM

#define QSCALE 16319.0f
#define XLIMB ((size_t)B_SZ * D_SZ)
#define WLIMB ((size_t)E_SZ * NPAD * D_SZ)

// gate split
#define GR 16
#define GP 4
#define DPG (D_SZ / GP)
#define GCH (DPG / 128)

// ---------------- scratch ----------------
__device__ int    g_cnt[E_SZ];
__device__ int    g_rows[E_SZ * B_SZ];
__device__ float  g_rw[E_SZ * B_SZ];
__device__ float  g_part[GP][B_SZ][E_SZ];
__device__ int8_t xq[2][XLIMB];            // x limbs [limb][row][k]
__device__ int8_t wq[2][WLIMB];            // W limbs [limb][e][n][k]
__device__ float  sxg[B_SZ];               // per-row x scale
__device__ float  swg[E_SZ * NPAD];        // per-(e,n) W scale
__device__ int    wmaxg[E_SZ * NPAD];      // float-bits col max (atomicMax)

// ---------------- helpers ----------------
__device__ __forceinline__ uint32_t smem_u32(const void* p) {
    uint32_t a;
    asm("{ .reg .u64 t; cvta.to.shared.u64 t, %1; cvt.u32.u64 %0, t; }"
        : "=r"(a) : "l"(p));
    return a;
}
__device__ __forceinline__ void cpa16(uint32_t dst, const void* src) {
    asm volatile("cp.async.ca.shared.global [%0], [%1], 16;"
                 :: "r"(dst), "l"(src));
}
#define CP_COMMIT() asm volatile("cp.async.commit_group;" ::: "memory")
#define CP_WAITN(n) asm volatile("cp.async.wait_group %0;" :: "n"(n) : "memory")
#define LDSM4(r, addr)                                                        \
    asm volatile("ldmatrix.sync.aligned.m8n8.x4.shared.b16 {%0,%1,%2,%3}, [%4];" \
                 : "=r"((r)[0]), "=r"((r)[1]), "=r"((r)[2]), "=r"((r)[3])     \
                 : "r"(addr))
#define IMMA(c, a, b0, b1)                                                    \
    asm volatile("mma.sync.aligned.m16n8k32.row.col.s32.s8.s8.s32 "           \
                 "{%0,%1,%2,%3}, {%4,%5,%6,%7}, {%8,%9}, {%0,%1,%2,%3};"      \
                 : "+r"((c)[0]), "+r"((c)[1]), "+r"((c)[2]), "+r"((c)[3])     \
                 : "r"((a)[0]), "r"((a)[1]), "r"((a)[2]), "r"((a)[3]),        \
                   "r"(b0), "r"(b1))

__device__ __forceinline__ uint32_t pack4(int a, int b, int c, int d) {
    return (uint32_t)(a & 255) | ((uint32_t)(b & 255) << 8) |
           ((uint32_t)(c & 255) << 16) | ((uint32_t)(d & 255) << 24);
}

// ---------------- kernel 1: zero output + counters + wmax ----------------
__global__ void zero_kernel(float4* __restrict__ out, int n4) {
    int i = blockIdx.x * blockDim.x + threadIdx.x;
    if (i < n4) out[i] = make_float4(0.f, 0.f, 0.f, 0.f);
    if (i < E_SZ) g_cnt[i] = 0;
    if (i < E_SZ * NPAD) wmaxg[i] = 0;
}

// ---------------- kernel 2: quantize x -> 2 s8 limbs + row scale -----------
__global__ __launch_bounds__(256) void quant_x(const float* __restrict__ x) {
    const int row = blockIdx.x;
    const int t   = threadIdx.x;
    __shared__ float red[256];

    const float4* xr = reinterpret_cast<const float4*>(x + (size_t)row * D_SZ);
    float4 v0 = xr[2 * t], v1 = xr[2 * t + 1];
    float m = fmaxf(fmaxf(fabsf(v0.x), fabsf(v0.y)), fmaxf(fabsf(v0.z), fabsf(v0.w)));
    m = fmaxf(m, fmaxf(fmaxf(fabsf(v1.x), fabsf(v1.y)), fmaxf(fabsf(v1.z), fabsf(v1.w))));
    red[t] = m;
    __syncthreads();
    for (int s = 128; s > 0; s >>= 1) {
        if (t < s) red[t] = fmaxf(red[t], red[t + s]);
        __syncthreads();
    }
    const float maxv = red[0];
    const float inv  = maxv > 0.f ? QSCALE / maxv : 0.f;

    float vv[8] = {v0.x, v0.y, v0.z, v0.w, v1.x, v1.y, v1.z, v1.w};
    int q1[8], q2[8];
#pragma unroll
    for (int i = 0; i < 8; i++) {
        float tv  = vv[i] * inv;
        float h   = rintf(tv * 0.0078125f);     // /128
        q1[i] = (int)h;
        q2[i] = (int)rintf(tv - 128.f * h);
    }
    uint2 p1 = make_uint2(pack4(q1[0], q1[1], q1[2], q1[3]),
                          pack4(q1[4], q1[5], q1[6], q1[7]));
    uint2 p2 = make_uint2(pack4(q2[0], q2[1], q2[2], q2[3]),
                          pack4(q2[4], q2[5], q2[6], q2[7]));
    *reinterpret_cast<uint2*>(&xq[0][(size_t)row * D_SZ + t * 8]) = p1;
    *reinterpret_cast<uint2*>(&xq[1][(size_t)row * D_SZ + t * 8]) = p2;
    if (t == 0) sxg[row] = maxv * (1.0f / QSCALE);
}

// ---------------- kernel 3: per-(e,n) column max of |We| --------------------
__global__ __launch_bounds__(256) void wmax_kernel(const float* __restrict__ We) {
    const int nb = blockIdx.x, kb = blockIdx.y, e = blockIdx.z;
    const int n = nb * 256 + threadIdx.x;
    if (n >= C_SZ) return;
    const float* src = We + ((size_t)e * D_SZ + kb * 256) * C_SZ + n;
    float m = 0.f;
#pragma unroll 4
    for (int k = 0; k < 256; k++)
        m = fmaxf(m, fabsf(src[(size_t)k * C_SZ]));
    atomicMax(&wmaxg[e * NPAD + n], __float_as_int(m));   // m >= 0
}

// ---------------- kernel 4: quantize+transpose We -> [e][n][k] limbs -------
// Coalesced-write version: block = 32 n x 256 k. Each thread quantizes 32
// CONTIGUOUS k for one n -> 8 threads cover 256B contiguous per (n, limb).
// (R14's version wrote 16B per 2KB stride: 76us. DRAM floor here is ~25us.)
__global__ __launch_bounds__(256) void quant_w(const float* __restrict__ We) {
    const int nb = blockIdx.x;     // 32 x 32n
    const int kb = blockIdx.y;     // 8 x 256k
    const int e  = blockIdx.z;
    const int t  = threadIdx.x;
    const int n0 = nb * 32, k0 = kb * 256;

    __shared__ float xs[256][33];
    for (int i = t; i < 256 * 32; i += 256) {
        int k = i >> 5, n = i & 31;
        xs[k][n] = (n0 + n < C_SZ)
            ? We[((size_t)e * D_SZ + k0 + k) * C_SZ + n0 + n] : 0.0f;
    }
    __syncthreads();

    const int n  = t >> 3;          // 0..31
    const int kc = (t & 7) * 32;    // 0..224
    const float mw  = __int_as_float(wmaxg[e * NPAD + n0 + n]);
    const float inv = mw > 0.f ? QSCALE / mw : 0.f;
    if (kb == 0 && kc == 0) swg[e * NPAD + n0 + n] = mw * (1.0f / QSCALE);

    uint32_t p1[8], p2[8];
#pragma unroll
    for (int g = 0; g < 8; g++) {
        int q1[4], q2[4];
#pragma unroll
        for (int j = 0; j < 4; j++) {
            float tv = xs[kc + g * 4 + j][n] * inv;
            float h  = rintf(tv * 0.0078125f);
            q1[j] = (int)h;
            q2[j] = (int)rintf(tv - 128.f * h);
        }
        p1[g] = pack4(q1[0], q1[1], q1[2], q1[3]);
        p2[g] = pack4(q2[0], q2[1], q2[2], q2[3]);
    }
    const size_t base = ((size_t)(e * NPAD + n0 + n)) * D_SZ + k0 + kc;
    *reinterpret_cast<uint4*>(&wq[0][base])      = make_uint4(p1[0], p1[1], p1[2], p1[3]);
    *reinterpret_cast<uint4*>(&wq[0][base + 16]) = make_uint4(p1[4], p1[5], p1[6], p1[7]);
    *reinterpret_cast<uint4*>(&wq[1][base])      = make_uint4(p2[0], p2[1], p2[2], p2[3]);
    *reinterpret_cast<uint4*>(&wq[1][base + 16]) = make_uint4(p2[4], p2[5], p2[6], p2[7]);
}

// ---------------- kernel 5: gate partials (split-D, unchanged) -------------
__global__ __launch_bounds__(256) void gate_part(
    const float* __restrict__ x, const float* __restrict__ Wr)
{
    __shared__ __align__(16) float xs[2][GR][132];
    __shared__ __align__(16) float wrs[2][E_SZ][132];

    const int tid   = threadIdx.x;
    const int row0  = blockIdx.x * GR;
    const int dbase = blockIdx.y * DPG;
    const int e     = tid & 15;
    const int r     = tid >> 4;

    const int xrow = tid >> 4;
    const int xseg = tid & 15;
    const float* xsrc = x + (size_t)(row0 + xrow) * D_SZ + dbase;
    const int wd = tid >> 1;
    const int we = (tid & 1) * 8;

    float4 wr0, wr1;
    auto ldg_wr = [&](int ch) {
        const float* p = Wr + (size_t)(dbase + ch * 128 + wd) * E_SZ + we;
        wr0 = *reinterpret_cast<const float4*>(p);
        wr1 = *reinterpret_cast<const float4*>(p + 4);
    };
    auto sts_wr = [&](int s) {
        wrs[s][we + 0][wd] = wr0.x; wrs[s][we + 1][wd] = wr0.y;
        wrs[s][we + 2][wd] = wr0.z; wrs[s][we + 3][wd] = wr0.w;
        wrs[s][we + 4][wd] = wr1.x; wrs[s][we + 5][wd] = wr1.y;
        wrs[s][we + 6][wd] = wr1.z; wrs[s][we + 7][wd] = wr1.w;
    };
    auto cpa_xs = [&](int ch, int s) {
        const int d0 = ch * 128;
        cpa16(smem_u32(&xs[s][xrow][xseg * 4]),        xsrc + d0 + xseg * 4);
        cpa16(smem_u32(&xs[s][xrow][(xseg + 16) * 4]), xsrc + d0 + (xseg + 16) * 4);
    };

    float acc0 = 0.0f, acc1 = 0.0f;

    ldg_wr(0);
    cpa_xs(0, 0); CP_COMMIT();
    for (int ch = 0; ch < GCH; ch++) {
        const int s = ch & 1;
        sts_wr(s);
        if (ch + 1 < GCH) {
            ldg_wr(ch + 1);
            cpa_xs(ch + 1, s ^ 1); CP_COMMIT();
            CP_WAITN(1);
        } else {
            CP_WAITN(0);
        }
        __syncthreads();
#pragma unroll
        for (int d = 0; d < 64; d += 4) {
            float4 xa = *reinterpret_cast<const float4*>(&xs[s][r][d]);
            float4 wa = *reinterpret_cast<const float4*>(&wrs[s][e][d]);
            acc0 += xa.x * wa.x + xa.y * wa.y + xa.z * wa.z + xa.w * wa.w;
            float4 xb = *reinterpret_cast<const float4*>(&xs[s][r][d + 64]);
            float4 wb = *reinterpret_cast<const float4*>(&wrs[s][e][d + 64]);
            acc1 += xb.x * wb.x + xb.y * wb.y + xb.z * wb.z + xb.w * wb.w;
        }
        __syncthreads();
    }
    g_part[blockIdx.y][row0 + r][e] = acc0 + acc1;
}

// ---------------- kernel 6: reduce partials + top-2 softmax + bucket -------
__global__ __launch_bounds__(256) void gate_reduce(const float* __restrict__ br) {
    const int row = blockIdx.x * 256 + threadIdx.x;
    if (row >= B_SZ) return;

    float lg[E_SZ];
#pragma unroll
    for (int q = 0; q < 4; q++) {
        float4 s = make_float4(0.f, 0.f, 0.f, 0.f);
#pragma unroll
        for (int p = 0; p < GP; p++) {
            float4 v = *reinterpret_cast<const float4*>(&g_part[p][row][q * 4]);
            s.x += v.x; s.y += v.y; s.z += v.z; s.w += v.w;
        }
        lg[q * 4 + 0] = s.x + br[q * 4 + 0];
        lg[q * 4 + 1] = s.y + br[q * 4 + 1];
        lg[q * 4 + 2] = s.z + br[q * 4 + 2];
        lg[q * 4 + 3] = s.w + br[q * 4 + 3];
    }

    float best = -1e30f; int bi = 0;
#pragma unroll
    for (int k = 0; k < E_SZ; k++)
        if (lg[k] > best) { best = lg[k]; bi = k; }
    float sec = -1e30f; int si = 0;
#pragma unroll
    for (int k = 0; k < E_SZ; k++) {
        if (k == bi) continue;
        if (lg[k] > sec) { sec = lg[k]; si = k; }
    }
    float t   = expf(sec - best);
    float inv = 1.0f / (1.0f + t);
    int p0 = atomicAdd(&g_cnt[bi], 1);
    g_rows[bi * B_SZ + p0] = row;  g_rw[bi * B_SZ + p0] = inv;
    int p1 = atomicAdd(&g_cnt[si], 1);
    g_rows[si * B_SZ + p1] = row;  g_rw[si * B_SZ + p1] = t * inv;
}

// ---------------- kernel 7: int8 limb IMMA grouped gather-GEMM -------------
// NST=3: each stage has ~2 chunks of compute to cover DRAM latency.
extern __shared__ char dynsmem[];

__global__ __launch_bounds__(256, 2) void expert_gemm_i8(
    const float* __restrict__ be, float* __restrict__ out)
{
    const int e   = blockIdx.z;
    const int cnt = g_cnt[e];
    const int m0  = blockIdx.y * TM;
    if (m0 >= cnt) return;
    const int n0  = blockIdx.x * TN;

    __shared__ int   rs[TM];
    __shared__ float ws[TM];
    __shared__ float sxs[TM];
    __shared__ float bes[TN];
    __shared__ float sws[TN];

    const int tid  = threadIdx.x;
    const int wid  = tid >> 5;
    const int lane = tid & 31;

    const uint32_t sb0 = smem_u32(dynsmem);

    for (int m = tid; m < TM; m += 256) {
        int gm = m0 + m; int rr = -1; float w = 0.0f; float sx = 0.0f;
        if (gm < cnt) {
            rr = g_rows[e * B_SZ + gm];
            w  = g_rw[e * B_SZ + gm];
            sx = sxg[rr];
        }
        rs[m] = rr; ws[m] = w; sxs[m] = sx;
    }
    if (tid < TN) {
        int c = n0 + tid;
        bes[tid] = (c < C_SZ) ? be[e * C_SZ + c] : 0.0f;
        sws[tid] = swg[e * NPAD + c];
    }
    __syncthreads();

    // ---- cp.async mappings: 6 x 16B per thread per chunk ----
    const int am = tid >> 1;
    const int as = (tid & 1) * 32;
    int ra = rs[am]; if (ra < 0) ra = 0;
    const int8_t* srcA = xq[0] + (size_t)ra * D_SZ + as;
    const uint32_t aoff = (uint32_t)(am * AROWB + as);
    const int bn = tid >> 2;
    const int bs = (tid & 3) * 16;
    const int8_t* srcB = wq[0] + ((size_t)(e * NPAD + n0 + bn)) * D_SZ + bs;
    const uint32_t boff = (uint32_t)(bn * AROWB + bs);

    auto issue_stage = [&](int c, int slot) {
        const uint32_t sb = sb0 + (uint32_t)slot * STAGE_B;
        const int ko = c * KC;
        cpa16(sb + OFF_A1 + aoff,      srcA + ko);
        cpa16(sb + OFF_A1 + aoff + 16, srcA + ko + 16);
        cpa16(sb + OFF_A2 + aoff,      srcA + XLIMB + ko);
        cpa16(sb + OFF_A2 + aoff + 16, srcA + XLIMB + ko + 16);
        cpa16(sb + OFF_B1 + boff, srcB + ko);
        cpa16(sb + OFF_B2 + boff, srcB + WLIMB + ko);
        CP_COMMIT();
    };

    // ---- compute mappings: 4m x 2n warp grid, 32x32 warp tiles ----
    const int warp_m = (wid & 3) * 32;
    const int warp_n = (wid >> 2) * 32;
    const uint32_t a_lds =
        (uint32_t)((warp_m + (lane & 15)) * AROWB + (lane >> 4) * 16);
    const uint32_t b_lds =
        (uint32_t)((warp_n + (lane & 15)) * AROWB + (lane >> 4) * 16);

    int acc1[2][4][4], acc2[2][4][4];
#pragma unroll
    for (int i = 0; i < 2; i++)
#pragma unroll
        for (int j = 0; j < 4; j++)
#pragma unroll
            for (int q = 0; q < 4; q++) { acc1[i][j][q] = 0; acc2[i][j][q] = 0; }

    auto compute_chunk = [&](int slot) {
        const uint32_t sb = sb0 + (uint32_t)slot * STAGE_B;
#pragma unroll
        for (int kk = 0; kk < 2; kk++) {
            const uint32_t koff = kk * 32;
            uint32_t a1[2][4], a2[2][4], b1f[2][4], b2f[2][4];
            LDSM4(b1f[0], sb + OFF_B1 + b_lds + koff);
            LDSM4(b1f[1], sb + OFF_B1 + b_lds + 16 * AROWB + koff);
            LDSM4(b2f[0], sb + OFF_B2 + b_lds + koff);
            LDSM4(b2f[1], sb + OFF_B2 + b_lds + 16 * AROWB + koff);
#pragma unroll
            for (int mt = 0; mt < 2; mt++) {
                const uint32_t ao = a_lds + mt * (16 * AROWB) + koff;
                LDSM4(a1[mt], sb + OFF_A1 + ao);
                LDSM4(a2[mt], sb + OFF_A2 + ao);
            }
#pragma unroll
            for (int mt = 0; mt < 2; mt++)
#pragma unroll
                for (int og = 0; og < 4; og++) {
                    const int g = og >> 1, j = og & 1;
                    const uint32_t p10 = b1f[g][j], p11 = b1f[g][j + 2];
                    const uint32_t p20 = b2f[g][j], p21 = b2f[g][j + 2];
                    IMMA(acc1[mt][og], a1[mt], p10, p11);
                    IMMA(acc2[mt][og], a1[mt], p20, p21);
                    IMMA(acc2[mt][og], a2[mt], p10, p11);
                }
        }
    };

    // ---- main loop: 3-stage pipeline, prefetch depth 2 ----
    // issue(c+2) targets slot (c-1)%3; the end-of-iteration barrier of the
    // previous chunk guarantees compute(c-1) is finished block-wide.
    issue_stage(0, 0);
    issue_stage(1, 1);
    for (int c = 0; c < NCHUNK; c++) {
        const int slot = c % NST;
        if (c + 2 < NCHUNK) {
            issue_stage(c + 2, (c + 2) % NST);
            CP_WAITN(2);
        } else if (c + 1 < NCHUNK) {
            CP_WAITN(1);
        } else {
            CP_WAITN(0);
        }
        __syncthreads();        // stage c visible block-wide
        compute_chunk(slot);
        __syncthreads();        // compute(c) done before slot reuse
    }

    // ---- epilogue: rescale + weighted atomic scatter ----
    const int gr = lane >> 2;
    const int gc = (lane & 3) * 2;
#pragma unroll
    for (int mt = 0; mt < 2; mt++) {
#pragma unroll
        for (int half = 0; half < 2; half++) {
            const int m = warp_m + mt * 16 + gr + half * 8;
            const int rr = rs[m];
            if (rr < 0) continue;
            const float w  = ws[m];
            const float sx = sxs[m];
            float* orow = out + (size_t)rr * C_SZ;
#pragma unroll
            for (int og = 0; og < 4; og++) {
                const int cc = warp_n + og * 8 + gc;
                const int c = n0 + cc;
                if (c >= C_SZ) continue;
                const float v0 = 16384.f * (float)acc1[mt][og][half * 2 + 0] +
                                 128.f   * (float)acc2[mt][og][half * 2 + 0];
                const float v1 = 16384.f * (float)acc1[mt][og][half * 2 + 1] +
                                 128.f   * (float)acc2[mt][og][half * 2 + 1];
                atomicAdd(orow + c,     w * (sx * sws[cc] * v0 + bes[cc]));
                if (c + 1 < C_SZ)
                    atomicAdd(orow + c + 1, w * (sx * sws[cc + 1] * v1 + bes[cc + 1]));
            }
        }
    }
}

// ---------------- launch ----------------
extern "C" void kernel_launch(void* const* d_in, const int* in_sizes, int n_in,
                              void* d_out, int out_size) {
    const float* x  = (const float*)d_in[0];
    const float* Wr = (const float*)d_in[1];
    const float* br = (const float*)d_in[2];
    const float* We = (const float*)d_in[3];
    const float* be = (const float*)d_in[4];
    float* out = (float*)d_out;

    cudaFuncSetAttribute(expert_gemm_i8,
                         cudaFuncAttributeMaxDynamicSharedMemorySize, DYN_BYTES);

    const int n4 = (B_SZ * C_SZ) / 4;
    zero_kernel<<<(n4 + 255) / 256, 256>>>((float4*)out, n4);
    quant_x<<<B_SZ, 256>>>(x);
    dim3 wmgrid((C_SZ + 255) / 256, D_SZ / 256, E_SZ);
    wmax_kernel<<<wmgrid, 256>>>(We);
    dim3 wqgrid(NPAD / 32, D_SZ / 256, E_SZ);
    quant_w<<<wqgrid, 256>>>(We);
    dim3 ggrid(B_SZ / GR, GP);
    gate_part<<<ggrid, 256>>>(x, Wr);
    gate_reduce<<<B_SZ / 256, 256>>>(br);
    dim3 grid(NPAD / TN, B_SZ / TM, E_SZ);
    expert_gemm_i8<<<grid, 256, DYN_BYTES>>>(be, out);
}

// round 16
// speedup vs baseline: 1.1112x; 1.1112x over previous
#include <cuda_runtime.h>
#include <cuda_bf16.h>
#include <cstdint>

#define B_SZ 4096
#define D_SZ 2048
#define E_SZ 16
#define C_SZ 1000
#define NPAD 1024

// int8 GEMM tiles
#define TM 128
#define TN 64
#define KC 64                    // s8 k per chunk
#define NCHUNK (D_SZ / KC)       // 32

// A smem: [m][k] rows of 64 s8 padded to 80B; B smem: [n][k] same
#define AROWB 80
#define A_TILE_B (128 * AROWB)   // 10240 per limb
#define B_TILE_B (64 * AROWB)    // 5120 per limb
#define OFF_A1 0
#define OFF_A2 A_TILE_B
#define OFF_B1 (2 * A_TILE_B)
#define OFF_B2 (2 * A_TILE_B + B_TILE_B)
#define STAGE_B (2 * A_TILE_B + 2 * B_TILE_B)   // 30720
#define NST 2
#define DYN_BYTES (NST * STAGE_B)               // 61440 -> 2 CTAs/SM

#define QSCALE 16319.0f
#define XLIMB ((size_t)B_SZ * D_SZ)
#define WLIMB ((size_t)E_SZ * NPAD * D_SZ)

// gate split
#define GR 16
#define GP 8
#define DPG (D_SZ / GP)          // 256
#define GCH (DPG / 128)          // 2

// quant_w smem pitch: 268 B/row (67 words) -> write banks 3*lane mod 32,
// all distinct (gcd(3,32)=1): conflict-free byte writes; reads 2-way worst.
#define QW_PITCH 268

// ---------------- scratch ----------------
__device__ int    g_cnt[E_SZ];
__device__ int    g_rows[E_SZ * B_SZ];
__device__ float  g_rw[E_SZ * B_SZ];
__device__ float  g_part[GP][B_SZ][E_SZ];
__device__ int8_t xq[2][XLIMB];            // x limbs [limb][row][k]
__device__ int8_t wq[2][WLIMB];            // W limbs [limb][e][n][k]
__device__ float  sxg[B_SZ];               // per-row x scale
__device__ float  swg[E_SZ * NPAD];        // per-(e,n) W scale
__device__ int    wmaxg[E_SZ * NPAD];      // float-bits col max (atomicMax)

// ---------------- helpers ----------------
__device__ __forceinline__ uint32_t smem_u32(const void* p) {
    uint32_t a;
    asm("{ .reg .u64 t; cvta.to.shared.u64 t, %1; cvt.u32.u64 %0, t; }"
        : "=r"(a) : "l"(p));
    return a;
}
__device__ __forceinline__ void cpa16(uint32_t dst, const void* src) {
    asm volatile("cp.async.ca.shared.global [%0], [%1], 16;"
                 :: "r"(dst), "l"(src));
}
#define CP_COMMIT() asm volatile("cp.async.commit_group;" ::: "memory")
#define CP_WAITN(n) asm volatile("cp.async.wait_group %0;" :: "n"(n) : "memory")
#define LDSM4(r, addr)                                                        \
    asm volatile("ldmatrix.sync.aligned.m8n8.x4.shared.b16 {%0,%1,%2,%3}, [%4];" \
                 : "=r"((r)[0]), "=r"((r)[1]), "=r"((r)[2]), "=r"((r)[3])     \
                 : "r"(addr))
#define IMMA(c, a, b0, b1)                                                    \
    asm volatile("mma.sync.aligned.m16n8k32.row.col.s32.s8.s8.s32 "           \
                 "{%0,%1,%2,%3}, {%4,%5,%6,%7}, {%8,%9}, {%0,%1,%2,%3};"      \
                 : "+r"((c)[0]), "+r"((c)[1]), "+r"((c)[2]), "+r"((c)[3])     \
                 : "r"((a)[0]), "r"((a)[1]), "r"((a)[2]), "r"((a)[3]),        \
                   "r"(b0), "r"(b1))

__device__ __forceinline__ uint32_t pack4(int a, int b, int c, int d) {
    return (uint32_t)(a & 255) | ((uint32_t)(b & 255) << 8) |
           ((uint32_t)(c & 255) << 16) | ((uint32_t)(d & 255) << 24);
}

// ---------------- kernel 1: zero output + counters + wmax ----------------
__global__ void zero_kernel(float4* __restrict__ out, int n4) {
    int i = blockIdx.x * blockDim.x + threadIdx.x;
    if (i < n4) out[i] = make_float4(0.f, 0.f, 0.f, 0.f);
    if (i < E_SZ) g_cnt[i] = 0;
    if (i < E_SZ * NPAD) wmaxg[i] = 0;
}

// ---------------- kernel 2: quantize x -> 2 s8 limbs + row scale -----------
__global__ __launch_bounds__(256) void quant_x(const float* __restrict__ x) {
    const int row = blockIdx.x;
    const int t   = threadIdx.x;
    __shared__ float red[256];

    const float4* xr = reinterpret_cast<const float4*>(x + (size_t)row * D_SZ);
    float4 v0 = xr[2 * t], v1 = xr[2 * t + 1];
    float m = fmaxf(fmaxf(fabsf(v0.x), fabsf(v0.y)), fmaxf(fabsf(v0.z), fabsf(v0.w)));
    m = fmaxf(m, fmaxf(fmaxf(fabsf(v1.x), fabsf(v1.y)), fmaxf(fabsf(v1.z), fabsf(v1.w))));
    red[t] = m;
    __syncthreads();
    for (int s = 128; s > 0; s >>= 1) {
        if (t < s) red[t] = fmaxf(red[t], red[t + s]);
        __syncthreads();
    }
    const float maxv = red[0];
    const float inv  = maxv > 0.f ? QSCALE / maxv : 0.f;

    float vv[8] = {v0.x, v0.y, v0.z, v0.w, v1.x, v1.y, v1.z, v1.w};
    int q1[8], q2[8];
#pragma unroll
    for (int i = 0; i < 8; i++) {
        float tv  = vv[i] * inv;
        float h   = rintf(tv * 0.0078125f);     // /128
        q1[i] = (int)h;
        q2[i] = (int)rintf(tv - 128.f * h);
    }
    uint2 p1 = make_uint2(pack4(q1[0], q1[1], q1[2], q1[3]),
                          pack4(q1[4], q1[5], q1[6], q1[7]));
    uint2 p2 = make_uint2(pack4(q2[0], q2[1], q2[2], q2[3]),
                          pack4(q2[4], q2[5], q2[6], q2[7]));
    *reinterpret_cast<uint2*>(&xq[0][(size_t)row * D_SZ + t * 8]) = p1;
    *reinterpret_cast<uint2*>(&xq[1][(size_t)row * D_SZ + t * 8]) = p2;
    if (t == 0) sxg[row] = maxv * (1.0f / QSCALE);
}

// ---------------- kernel 3: per-(e,n) column max of |We| --------------------
__global__ __launch_bounds__(256) void wmax_kernel(const float* __restrict__ We) {
    const int nb = blockIdx.x, kb = blockIdx.y, e = blockIdx.z;
    const int n = nb * 256 + threadIdx.x;
    if (n >= C_SZ) return;
    const float* src = We + ((size_t)e * D_SZ + kb * 256) * C_SZ + n;
    float m = 0.f;
#pragma unroll 4
    for (int k = 0; k < 256; k++)
        m = fmaxf(m, fabsf(src[(size_t)k * C_SZ]));
    atomicMax(&wmaxg[e * NPAD + n], __float_as_int(m));   // m >= 0
}

// ---------------- kernel 4: quantize+transpose We -> [e][n][k] limbs -------
// Quantize-in-registers, byte-smem transpose, coalesced gmem both directions.
// Phase A: lane = n (coalesced 128B row reads); quantize elementwise; byte
//   writes to sq[n][k] pitch 268 -> banks 3*lane mod 32, conflict-free.
// Phase B: thread owns (n = t>>3, kc = (t&7)*32); 4B smem reads (2-way worst);
//   two 16B gmem stores per limb -> 8 threads cover 256B contiguous per n.
__global__ __launch_bounds__(256) void quant_w(const float* __restrict__ We) {
    const int nb = blockIdx.x;     // 32 x 32n
    const int kb = blockIdx.y;     // 8 x 256k
    const int e  = blockIdx.z;
    const int t  = threadIdx.x;
    const int n0 = nb * 32, k0 = kb * 256;

    __shared__ int8_t sq1[32 * QW_PITCH];
    __shared__ int8_t sq2[32 * QW_PITCH];

    // Phase A
    {
        const int n  = t & 31;
        const int kb8 = t >> 5;                 // 0..7
        const bool nv = (n0 + n) < C_SZ;
        const float mw  = nv ? __int_as_float(wmaxg[e * NPAD + n0 + n]) : 0.f;
        const float inv = mw > 0.f ? QSCALE / mw : 0.f;
        const float* src = We + ((size_t)e * D_SZ + k0) * C_SZ + n0 + n;
        int8_t* r1 = sq1 + n * QW_PITCH;
        int8_t* r2 = sq2 + n * QW_PITCH;
#pragma unroll 8
        for (int it = 0; it < 32; it++) {
            const int k = kb8 + it * 8;
            float v = nv ? src[(size_t)k * C_SZ] : 0.0f;
            float tv = v * inv;
            float h  = rintf(tv * 0.0078125f);
            r1[k] = (int8_t)(int)h;
            r2[k] = (int8_t)(int)rintf(tv - 128.f * h);
        }
    }
    __syncthreads();

    // Phase B
    {
        const int n  = t >> 3;                  // 0..31
        const int kc = (t & 7) * 32;            // 0..224
        if (kb == 0 && kc == 0) {
            const bool nv = (n0 + n) < C_SZ;
            const float mw = nv ? __int_as_float(wmaxg[e * NPAD + n0 + n]) : 0.f;
            swg[e * NPAD + n0 + n] = mw * (1.0f / QSCALE);
        }
        const uint32_t s1 = smem_u32(sq1) + n * QW_PITCH + kc;
        const uint32_t s2 = smem_u32(sq2) + n * QW_PITCH + kc;
        uint32_t w1[8], w2[8];
#pragma unroll
        for (int j = 0; j < 8; j++) {
            asm volatile("ld.shared.b32 %0, [%1];" : "=r"(w1[j]) : "r"(s1 + 4 * j));
            asm volatile("ld.shared.b32 %0, [%1];" : "=r"(w2[j]) : "r"(s2 + 4 * j));
        }
        const size_t base = ((size_t)(e * NPAD + n0 + n)) * D_SZ + k0 + kc;
        *reinterpret_cast<uint4*>(&wq[0][base])      = make_uint4(w1[0], w1[1], w1[2], w1[3]);
        *reinterpret_cast<uint4*>(&wq[0][base + 16]) = make_uint4(w1[4], w1[5], w1[6], w1[7]);
        *reinterpret_cast<uint4*>(&wq[1][base])      = make_uint4(w2[0], w2[1], w2[2], w2[3]);
        *reinterpret_cast<uint4*>(&wq[1][base + 16]) = make_uint4(w2[4], w2[5], w2[6], w2[7]);
    }
}

// ---------------- kernel 5: gate partials (split-D, GP=8) ------------------
__global__ __launch_bounds__(256) void gate_part(
    const float* __restrict__ x, const float* __restrict__ Wr)
{
    __shared__ __align__(16) float xs[2][GR][132];
    __shared__ __align__(16) float wrs[2][E_SZ][132];

    const int tid   = threadIdx.x;
    const int row0  = blockIdx.x * GR;
    const int dbase = blockIdx.y * DPG;
    const int e     = tid & 15;
    const int r     = tid >> 4;

    const int xrow = tid >> 4;
    const int xseg = tid & 15;
    const float* xsrc = x + (size_t)(row0 + xrow) * D_SZ + dbase;
    const int wd = tid >> 1;
    const int we = (tid & 1) * 8;

    float4 wr0, wr1;
    auto ldg_wr = [&](int ch) {
        const float* p = Wr + (size_t)(dbase + ch * 128 + wd) * E_SZ + we;
        wr0 = *reinterpret_cast<const float4*>(p);
        wr1 = *reinterpret_cast<const float4*>(p + 4);
    };
    auto sts_wr = [&](int s) {
        wrs[s][we + 0][wd] = wr0.x; wrs[s][we + 1][wd] = wr0.y;
        wrs[s][we + 2][wd] = wr0.z; wrs[s][we + 3][wd] = wr0.w;
        wrs[s][we + 4][wd] = wr1.x; wrs[s][we + 5][wd] = wr1.y;
        wrs[s][we + 6][wd] = wr1.z; wrs[s][we + 7][wd] = wr1.w;
    };
    auto cpa_xs = [&](int ch, int s) {
        const int d0 = ch * 128;
        cpa16(smem_u32(&xs[s][xrow][xseg * 4]),        xsrc + d0 + xseg * 4);
        cpa16(smem_u32(&xs[s][xrow][(xseg + 16) * 4]), xsrc + d0 + (xseg + 16) * 4);
    };

    float acc0 = 0.0f, acc1 = 0.0f;

    ldg_wr(0);
    cpa_xs(0, 0); CP_COMMIT();
    for (int ch = 0; ch < GCH; ch++) {
        const int s = ch & 1;
        sts_wr(s);
        if (ch + 1 < GCH) {
            ldg_wr(ch + 1);
            cpa_xs(ch + 1, s ^ 1); CP_COMMIT();
            CP_WAITN(1);
        } else {
            CP_WAITN(0);
        }
        __syncthreads();
#pragma unroll
        for (int d = 0; d < 64; d += 4) {
            float4 xa = *reinterpret_cast<const float4*>(&xs[s][r][d]);
            float4 wa = *reinterpret_cast<const float4*>(&wrs[s][e][d]);
            acc0 += xa.x * wa.x + xa.y * wa.y + xa.z * wa.z + xa.w * wa.w;
            float4 xb = *reinterpret_cast<const float4*>(&xs[s][r][d + 64]);
            float4 wb = *reinterpret_cast<const float4*>(&wrs[s][e][d + 64]);
            acc1 += xb.x * wb.x + xb.y * wb.y + xb.z * wb.z + xb.w * wb.w;
        }
        __syncthreads();
    }
    g_part[blockIdx.y][row0 + r][e] = acc0 + acc1;
}

// ---------------- kernel 6: reduce partials + top-2 softmax + bucket -------
__global__ __launch_bounds__(256) void gate_reduce(const float* __restrict__ br) {
    const int row = blockIdx.x * 256 + threadIdx.x;
    if (row >= B_SZ) return;

    float lg[E_SZ];
#pragma unroll
    for (int q = 0; q < 4; q++) {
        float4 s = make_float4(0.f, 0.f, 0.f, 0.f);
#pragma unroll
        for (int p = 0; p < GP; p++) {        // fixed order -> deterministic
            float4 v = *reinterpret_cast<const float4*>(&g_part[p][row][q * 4]);
            s.x += v.x; s.y += v.y; s.z += v.z; s.w += v.w;
        }
        lg[q * 4 + 0] = s.x + br[q * 4 + 0];
        lg[q * 4 + 1] = s.y + br[q * 4 + 1];
        lg[q * 4 + 2] = s.z + br[q * 4 + 2];
        lg[q * 4 + 3] = s.w + br[q * 4 + 3];
    }

    float best = -1e30f; int bi = 0;
#pragma unroll
    for (int k = 0; k < E_SZ; k++)
        if (lg[k] > best) { best = lg[k]; bi = k; }
    float sec = -1e30f; int si = 0;
#pragma unroll
    for (int k = 0; k < E_SZ; k++) {
        if (k == bi) continue;
        if (lg[k] > sec) { sec = lg[k]; si = k; }
    }
    float t   = expf(sec - best);
    float inv = 1.0f / (1.0f + t);
    int p0 = atomicAdd(&g_cnt[bi], 1);
    g_rows[bi * B_SZ + p0] = row;  g_rw[bi * B_SZ + p0] = inv;
    int p1 = atomicAdd(&g_cnt[si], 1);
    g_rows[si * B_SZ + p1] = row;  g_rw[si * B_SZ + p1] = t * inv;
}

// ---------------- kernel 7: int8 limb IMMA grouped gather-GEMM -------------
// R14 loop (NST=2) restored: measured best (GEMM ~246us; NST=3 regressed).
extern __shared__ char dynsmem[];

__global__ __launch_bounds__(256, 2) void expert_gemm_i8(
    const float* __restrict__ be, float* __restrict__ out)
{
    const int e   = blockIdx.z;
    const int cnt = g_cnt[e];
    const int m0  = blockIdx.y * TM;
    if (m0 >= cnt) return;
    const int n0  = blockIdx.x * TN;

    __shared__ int   rs[TM];
    __shared__ float ws[TM];
    __shared__ float sxs[TM];
    __shared__ float bes[TN];
    __shared__ float sws[TN];

    const int tid  = threadIdx.x;
    const int wid  = tid >> 5;
    const int lane = tid & 31;

    const uint32_t sb0 = smem_u32(dynsmem);

    for (int m = tid; m < TM; m += 256) {
        int gm = m0 + m; int rr = -1; float w = 0.0f; float sx = 0.0f;
        if (gm < cnt) {
            rr = g_rows[e * B_SZ + gm];
            w  = g_rw[e * B_SZ + gm];
            sx = sxg[rr];
        }
        rs[m] = rr; ws[m] = w; sxs[m] = sx;
    }
    if (tid < TN) {
        int c = n0 + tid;
        bes[tid] = (c < C_SZ) ? be[e * C_SZ + c] : 0.0f;
        sws[tid] = swg[e * NPAD + c];
    }
    __syncthreads();

    // ---- cp.async mappings: 6 x 16B per thread per chunk ----
    const int am = tid >> 1;
    const int as = (tid & 1) * 32;
    int ra = rs[am]; if (ra < 0) ra = 0;
    const int8_t* srcA = xq[0] + (size_t)ra * D_SZ + as;
    const uint32_t aoff = (uint32_t)(am * AROWB + as);
    const int bn = tid >> 2;
    const int bs = (tid & 3) * 16;
    const int8_t* srcB = wq[0] + ((size_t)(e * NPAD + n0 + bn)) * D_SZ + bs;
    const uint32_t boff = (uint32_t)(bn * AROWB + bs);

    auto issue_stage = [&](int c, int slot) {
        const uint32_t sb = sb0 + (uint32_t)slot * STAGE_B;
        const int ko = c * KC;
        cpa16(sb + OFF_A1 + aoff,      srcA + ko);
        cpa16(sb + OFF_A1 + aoff + 16, srcA + ko + 16);
        cpa16(sb + OFF_A2 + aoff,      srcA + XLIMB + ko);
        cpa16(sb + OFF_A2 + aoff + 16, srcA + XLIMB + ko + 16);
        cpa16(sb + OFF_B1 + boff, srcB + ko);
        cpa16(sb + OFF_B2 + boff, srcB + WLIMB + ko);
        CP_COMMIT();
    };

    // ---- compute mappings: 4m x 2n warp grid, 32x32 warp tiles ----
    const int warp_m = (wid & 3) * 32;
    const int warp_n = (wid >> 2) * 32;
    const uint32_t a_lds =
        (uint32_t)((warp_m + (lane & 15)) * AROWB + (lane >> 4) * 16);
    const uint32_t b_lds =
        (uint32_t)((warp_n + (lane & 15)) * AROWB + (lane >> 4) * 16);

    int acc1[2][4][4], acc2[2][4][4];
#pragma unroll
    for (int i = 0; i < 2; i++)
#pragma unroll
        for (int j = 0; j < 4; j++)
#pragma unroll
            for (int q = 0; q < 4; q++) { acc1[i][j][q] = 0; acc2[i][j][q] = 0; }

    auto compute_chunk = [&](int slot) {
        const uint32_t sb = sb0 + (uint32_t)slot * STAGE_B;
#pragma unroll
        for (int kk = 0; kk < 2; kk++) {
            const uint32_t koff = kk * 32;
            uint32_t a1[2][4], a2[2][4], b1f[2][4], b2f[2][4];
            LDSM4(b1f[0], sb + OFF_B1 + b_lds + koff);
            LDSM4(b1f[1], sb + OFF_B1 + b_lds + 16 * AROWB + koff);
            LDSM4(b2f[0], sb + OFF_B2 + b_lds + koff);
            LDSM4(b2f[1], sb + OFF_B2 + b_lds + 16 * AROWB + koff);
#pragma unroll
            for (int mt = 0; mt < 2; mt++) {
                const uint32_t ao = a_lds + mt * (16 * AROWB) + koff;
                LDSM4(a1[mt], sb + OFF_A1 + ao);
                LDSM4(a2[mt], sb + OFF_A2 + ao);
            }
#pragma unroll
            for (int mt = 0; mt < 2; mt++)
#pragma unroll
                for (int og = 0; og < 4; og++) {
                    const int g = og >> 1, j = og & 1;
                    const uint32_t p10 = b1f[g][j], p11 = b1f[g][j + 2];
                    const uint32_t p20 = b2f[g][j], p21 = b2f[g][j + 2];
                    IMMA(acc1[mt][og], a1[mt], p10, p11);
                    IMMA(acc2[mt][og], a1[mt], p20, p21);
                    IMMA(acc2[mt][og], a2[mt], p10, p11);
                }
        }
    };

    // ---- main loop: 2-stage pipeline ----
    issue_stage(0, 0);
    for (int c = 0; c < NCHUNK; c++) {
        const int slot = c & 1;
        if (c + 1 < NCHUNK) {
            issue_stage(c + 1, slot ^ 1);
            CP_WAITN(1);
        } else {
            CP_WAITN(0);
        }
        __syncthreads();
        compute_chunk(slot);
        __syncthreads();
    }

    // ---- epilogue: rescale + weighted atomic scatter ----
    const int gr = lane >> 2;
    const int gc = (lane & 3) * 2;
#pragma unroll
    for (int mt = 0; mt < 2; mt++) {
#pragma unroll
        for (int half = 0; half < 2; half++) {
            const int m = warp_m + mt * 16 + gr + half * 8;
            const int rr = rs[m];
            if (rr < 0) continue;
            const float w  = ws[m];
            const float sx = sxs[m];
            float* orow = out + (size_t)rr * C_SZ;
#pragma unroll
            for (int og = 0; og < 4; og++) {
                const int cc = warp_n + og * 8 + gc;
                const int c = n0 + cc;
                if (c >= C_SZ) continue;
                const float v0 = 16384.f * (float)acc1[mt][og][half * 2 + 0] +
                                 128.f   * (float)acc2[mt][og][half * 2 + 0];
                const float v1 = 16384.f * (float)acc1[mt][og][half * 2 + 1] +
                                 128.f   * (float)acc2[mt][og][half * 2 + 1];
                atomicAdd(orow + c,     w * (sx * sws[cc] * v0 + bes[cc]));
                if (c + 1 < C_SZ)
                    atomicAdd(orow + c + 1, w * (sx * sws[cc + 1] * v1 + bes[cc + 1]));
            }
        }
    }
}

// ---------------- launch ----------------
extern "C" void kernel_launch(void* const* d_in, const int* in_sizes, int n_in,
                              void* d_out, int out_size) {
    const float* x  = (const float*)d_in[0];
    const float* Wr = (const float*)d_in[1];
    const float* br = (const float*)d_in[2];
    const float* We = (const float*)d_in[3];
    const float* be = (const float*)d_in[4];
    float* out = (float*)d_out;

    cudaFuncSetAttribute(expert_gemm_i8,
                         cudaFuncAttributeMaxDynamicSharedMemorySize, DYN_BYTES);

    const int n4 = (B_SZ * C_SZ) / 4;
    zero_kernel<<<(n4 + 255) / 256, 256>>>((float4*)out, n4);
    quant_x<<<B_SZ, 256>>>(x);
    dim3 wmgrid((C_SZ + 255) / 256, D_SZ / 256, E_SZ);
    wmax_kernel<<<wmgrid, 256>>>(We);
    dim3 wqgrid(NPAD / 32, D_SZ / 256, E_SZ);
    quant_w<<<wqgrid, 256>>>(We);
    dim3 ggrid(B_SZ / GR, GP);
    gate_part<<<ggrid, 256>>>(x, Wr);
    gate_reduce<<<B_SZ / 256, 256>>>(br);
    dim3 grid(NPAD / TN, B_SZ / TM, E_SZ);
    expert_gemm_i8<<<grid, 256, DYN_BYTES>>>(be, out);
}